// round 1
// baseline (speedup 1.0000x reference)
#include <cuda_runtime.h>

#define B_   4096
#define T_   17
#define C_   512
#define D_   512
#define KCAT 1024   // [seasonal | trend] concatenated along K

// Scratch (device globals — no runtime allocation allowed)
__device__ float g_Acat[(size_t)T_ * B_ * KCAT];   // [T][B][1024]  (~285 MB)
__device__ float g_Wcat[(size_t)T_ * D_ * KCAT];   // [T][512][1024] (~36 MB)
__device__ float g_bias[T_ * D_];

// ---------------------------------------------------------------------------
// Prep: trend[b,t] = (S_b + (18-t)*x0 + (t+2)*x16)/37 ; seasonal = x - trend.
// One block per b, 128 threads = one float4 of C each.
// ---------------------------------------------------------------------------
__global__ void prep_kernel(const float* __restrict__ x) {
    const int b  = blockIdx.x;
    const int c4 = threadIdx.x;  // 0..127
    const float4* xb = reinterpret_cast<const float4*>(x) + (size_t)b * (T_ * C_ / 4);

    float4 v[T_];
    float sx = 0.f, sy = 0.f, sz = 0.f, sw = 0.f;
#pragma unroll
    for (int t = 0; t < T_; ++t) {
        v[t] = xb[t * (C_ / 4) + c4];
        sx += v[t].x; sy += v[t].y; sz += v[t].z; sw += v[t].w;
    }
    const float4 x0 = v[0];
    const float4 xl = v[T_ - 1];
    const float inv = 1.0f / 37.0f;

#pragma unroll
    for (int t = 0; t < T_; ++t) {
        const float a = (float)(18 - t);
        const float c = (float)(t + 2);
        float4 tr;
        tr.x = (sx + a * x0.x + c * xl.x) * inv;
        tr.y = (sy + a * x0.y + c * xl.y) * inv;
        tr.z = (sz + a * x0.z + c * xl.z) * inv;
        tr.w = (sw + a * x0.w + c * xl.w) * inv;
        float4 se;
        se.x = v[t].x - tr.x;
        se.y = v[t].y - tr.y;
        se.z = v[t].z - tr.z;
        se.w = v[t].w - tr.w;
        float4* dst = reinterpret_cast<float4*>(g_Acat + ((size_t)t * B_ + b) * KCAT);
        dst[c4]              = se;   // seasonal in K[0:512)
        dst[(C_ / 4) + c4]   = tr;   // trend    in K[512:1024)
    }
}

// ---------------------------------------------------------------------------
// Build Wcat[t][d] = [W_seasonal[t][d] | W_trend[t][d]] and bias = b_s + b_t.
// ---------------------------------------------------------------------------
__global__ void wcat_kernel(const float* __restrict__ Ws, const float* __restrict__ Wt,
                            const float* __restrict__ bs, const float* __restrict__ bt) {
    const size_t total = (size_t)T_ * D_ * (C_ / 4);
    size_t i = (size_t)blockIdx.x * blockDim.x + threadIdx.x;
    if (i < total) {
        const size_t row = i / (C_ / 4);
        const int    c4  = (int)(i % (C_ / 4));
        float4 s = reinterpret_cast<const float4*>(Ws)[i];
        float4 t = reinterpret_cast<const float4*>(Wt)[i];
        float4* w = reinterpret_cast<float4*>(g_Wcat) + row * (KCAT / 4);
        w[c4]            = s;
        w[(C_ / 4) + c4] = t;
    }
    if (i < (size_t)T_ * D_) {
        g_bias[i] = bs[i] + bt[i];
    }
}

// ---------------------------------------------------------------------------
// Grouped SGEMM: per t, out[b,d] = sum_k Acat[b,k]*Wcat[d,k] + bias[t,d]
// 128x128 block tile, BK=16, 256 threads, 8x8 per-thread microtile.
// ---------------------------------------------------------------------------
__global__ __launch_bounds__(256, 2) void gemm_kernel(float* __restrict__ out) {
    const int t  = blockIdx.z;
    const int bm = blockIdx.y;  // 0..31  (M = 4096)
    const int bn = blockIdx.x;  // 0..3   (N = 512)

    const float* Ag = g_Acat + ((size_t)t * B_ + (size_t)bm * 128) * KCAT;
    const float* Bg = g_Wcat + ((size_t)t * D_ + (size_t)bn * 128) * KCAT;

    __shared__ float As[16][128];
    __shared__ float Bs[16][128];

    const int tid  = threadIdx.x;
    const int lrow = tid >> 2;         // 0..63
    const int lcol = (tid & 3) << 2;   // 0,4,8,12
    const int tx   = tid & 15;         // micro col group
    const int ty   = tid >> 4;         // micro row group

    float acc[8][8];
#pragma unroll
    for (int i = 0; i < 8; ++i)
#pragma unroll
        for (int j = 0; j < 8; ++j) acc[i][j] = 0.f;

    for (int k0 = 0; k0 < KCAT; k0 += 16) {
        const float4 a0 = *reinterpret_cast<const float4*>(Ag + (size_t)lrow * KCAT + k0 + lcol);
        const float4 a1 = *reinterpret_cast<const float4*>(Ag + (size_t)(lrow + 64) * KCAT + k0 + lcol);
        const float4 b0 = *reinterpret_cast<const float4*>(Bg + (size_t)lrow * KCAT + k0 + lcol);
        const float4 b1 = *reinterpret_cast<const float4*>(Bg + (size_t)(lrow + 64) * KCAT + k0 + lcol);

        __syncthreads();  // previous iteration's reads complete
        As[lcol + 0][lrow] = a0.x; As[lcol + 1][lrow] = a0.y;
        As[lcol + 2][lrow] = a0.z; As[lcol + 3][lrow] = a0.w;
        As[lcol + 0][lrow + 64] = a1.x; As[lcol + 1][lrow + 64] = a1.y;
        As[lcol + 2][lrow + 64] = a1.z; As[lcol + 3][lrow + 64] = a1.w;
        Bs[lcol + 0][lrow] = b0.x; Bs[lcol + 1][lrow] = b0.y;
        Bs[lcol + 2][lrow] = b0.z; Bs[lcol + 3][lrow] = b0.w;
        Bs[lcol + 0][lrow + 64] = b1.x; Bs[lcol + 1][lrow + 64] = b1.y;
        Bs[lcol + 2][lrow + 64] = b1.z; Bs[lcol + 3][lrow + 64] = b1.w;
        __syncthreads();

#pragma unroll
        for (int k = 0; k < 16; ++k) {
            float ar[8], br[8];
#pragma unroll
            for (int i = 0; i < 8; ++i) ar[i] = As[k][ty * 8 + i];
#pragma unroll
            for (int j = 0; j < 8; ++j) br[j] = Bs[k][tx * 8 + j];
#pragma unroll
            for (int i = 0; i < 8; ++i)
#pragma unroll
                for (int j = 0; j < 8; ++j) acc[i][j] += ar[i] * br[j];
        }
    }

    // Epilogue: add bias, write out[b, t, d] (row stride T_*D_)
    const int colBase = bn * 128 + tx * 8;
    const float4 bv0 = *reinterpret_cast<const float4*>(g_bias + t * D_ + colBase);
    const float4 bv1 = *reinterpret_cast<const float4*>(g_bias + t * D_ + colBase + 4);

#pragma unroll
    for (int i = 0; i < 8; ++i) {
        const int row = bm * 128 + ty * 8 + i;
        float* op = out + (size_t)row * (T_ * D_) + (size_t)t * D_ + colBase;
        float4 o0, o1;
        o0.x = acc[i][0] + bv0.x; o0.y = acc[i][1] + bv0.y;
        o0.z = acc[i][2] + bv0.z; o0.w = acc[i][3] + bv0.w;
        o1.x = acc[i][4] + bv1.x; o1.y = acc[i][5] + bv1.y;
        o1.z = acc[i][6] + bv1.z; o1.w = acc[i][7] + bv1.w;
        *reinterpret_cast<float4*>(op)     = o0;
        *reinterpret_cast<float4*>(op + 4) = o1;
    }
}

// ---------------------------------------------------------------------------
extern "C" void kernel_launch(void* const* d_in, const int* in_sizes, int n_in,
                              void* d_out, int out_size) {
    const float* x  = (const float*)d_in[0];
    const float* Ws = (const float*)d_in[1];
    const float* bs = (const float*)d_in[2];
    const float* Wt = (const float*)d_in[3];
    const float* bt = (const float*)d_in[4];
    float* out = (float*)d_out;

    prep_kernel<<<B_, 128>>>(x);

    const int wthreads = 256;
    const size_t wtotal = (size_t)T_ * D_ * (C_ / 4);
    wcat_kernel<<<(unsigned)((wtotal + wthreads - 1) / wthreads), wthreads>>>(Ws, Wt, bs, bt);

    dim3 grid(D_ / 128, B_ / 128, T_);
    gemm_kernel<<<grid, 256>>>(out);
}

// round 3
// speedup vs baseline: 2.5010x; 2.5010x over previous
#include <cuda_runtime.h>
#include <cuda_bf16.h>
#include <cstdint>

#define Tn 17
#define Bn 4096
#define Cn 512
#define Dn 512
#define Kn 1024          // [seasonal | trend] along K
#define TILE_M 128
#define TILE_N 128
#define BK 64            // K elems per stage (128 bytes/row)
#define NSTAGE (Kn / BK) // 16
#define PIPE 3           // smem buffers

// -------------------- scratch (device globals; no runtime alloc) ------------
__device__ __align__(256) __nv_bfloat16 g_Ah[(size_t)Tn * Bn * Kn];  // ~143 MB
__device__ __align__(256) __nv_bfloat16 g_Al[(size_t)Tn * Bn * Kn];  // ~143 MB
__device__ __align__(256) __nv_bfloat16 g_Wh[(size_t)Tn * Dn * Kn];  // ~18 MB
__device__ __align__(256) __nv_bfloat16 g_Wl[(size_t)Tn * Dn * Kn];  // ~18 MB
__device__ float g_bias[Tn * Dn];

// -------------------- helpers ------------------------------------------------
__device__ __forceinline__ uint32_t smem_u32(const void* p) {
    uint32_t a;
    asm("{ .reg .u64 t; cvta.to.shared.u64 t, %1; cvt.u32.u64 %0, t; }"
        : "=r"(a) : "l"(p));
    return a;
}

#define SWZ(o) ((o) ^ (((o) >> 3) & 0x70))

#define CP16(smem_addr, gptr) \
    asm volatile("cp.async.cg.shared.global [%0], [%1], 16;" \
                 :: "r"((uint32_t)(smem_addr)), "l"(gptr) : "memory")
#define CP_COMMIT()  asm volatile("cp.async.commit_group;" ::: "memory")
#define CP_WAIT_1()  asm volatile("cp.async.wait_group 1;" ::: "memory")
#define CP_WAIT_0()  asm volatile("cp.async.wait_group 0;" ::: "memory")

__device__ __forceinline__ void ldsm4(uint32_t* r, uint32_t addr) {
    asm volatile("ldmatrix.sync.aligned.m8n8.x4.shared.b16 {%0,%1,%2,%3}, [%4];"
                 : "=r"(r[0]), "=r"(r[1]), "=r"(r[2]), "=r"(r[3]) : "r"(addr));
}

__device__ __forceinline__ void mma16816(float* c, const uint32_t* a,
                                         uint32_t b0, uint32_t b1) {
    asm volatile(
        "mma.sync.aligned.m16n8k16.row.col.f32.bf16.bf16.f32 "
        "{%0,%1,%2,%3}, {%4,%5,%6,%7}, {%8,%9}, {%0,%1,%2,%3};"
        : "+f"(c[0]), "+f"(c[1]), "+f"(c[2]), "+f"(c[3])
        : "r"(a[0]), "r"(a[1]), "r"(a[2]), "r"(a[3]), "r"(b0), "r"(b1));
}

// SMEM: PIPE stages x (Ah 16K | Al 16K | Bh 16K | Bl 16K) = 3 x 64K = 192K
#define STAGE_BYTES 65536u
#define SMEM_TOTAL  (PIPE * STAGE_BYTES)

// -------------------- prep: seasonal/trend -> bf16 hi/lo --------------------
__device__ __forceinline__ void write_hl(__nv_bfloat16* ph, __nv_bfloat16* pl, float4 v) {
    float a[4] = {v.x, v.y, v.z, v.w};
    uint2 uh, ul;
    unsigned short h[4], l[4];
#pragma unroll
    for (int i = 0; i < 4; ++i) {
        __nv_bfloat16 hb = __float2bfloat16(a[i]);
        __nv_bfloat16 lb = __float2bfloat16(a[i] - __bfloat162float(hb));
        h[i] = __bfloat16_as_ushort(hb);
        l[i] = __bfloat16_as_ushort(lb);
    }
    uh.x = (uint32_t)h[0] | ((uint32_t)h[1] << 16);
    uh.y = (uint32_t)h[2] | ((uint32_t)h[3] << 16);
    ul.x = (uint32_t)l[0] | ((uint32_t)l[1] << 16);
    ul.y = (uint32_t)l[2] | ((uint32_t)l[3] << 16);
    *reinterpret_cast<uint2*>(ph) = uh;
    *reinterpret_cast<uint2*>(pl) = ul;
}

__global__ void prep_kernel(const float* __restrict__ x) {
    const int b  = blockIdx.x;
    const int c4 = threadIdx.x;  // 0..127
    const float4* xb = reinterpret_cast<const float4*>(x) + (size_t)b * (Tn * Cn / 4);

    float4 v[Tn];
    float sx = 0.f, sy = 0.f, sz = 0.f, sw = 0.f;
#pragma unroll
    for (int t = 0; t < Tn; ++t) {
        v[t] = xb[t * (Cn / 4) + c4];
        sx += v[t].x; sy += v[t].y; sz += v[t].z; sw += v[t].w;
    }
    const float4 x0 = v[0];
    const float4 xl = v[Tn - 1];
    const float inv = 1.0f / 37.0f;

#pragma unroll
    for (int t = 0; t < Tn; ++t) {
        const float a = (float)(18 - t);
        const float c = (float)(t + 2);
        float4 tr, se;
        tr.x = (sx + a * x0.x + c * xl.x) * inv;
        tr.y = (sy + a * x0.y + c * xl.y) * inv;
        tr.z = (sz + a * x0.z + c * xl.z) * inv;
        tr.w = (sw + a * x0.w + c * xl.w) * inv;
        se.x = v[t].x - tr.x; se.y = v[t].y - tr.y;
        se.z = v[t].z - tr.z; se.w = v[t].w - tr.w;
        const size_t row = ((size_t)t * Bn + b) * Kn;
        write_hl(g_Ah + row + c4 * 4,       g_Al + row + c4 * 4,       se);
        write_hl(g_Ah + row + 512 + c4 * 4, g_Al + row + 512 + c4 * 4, tr);
    }
}

__global__ void wprep_kernel(const float* __restrict__ Ws, const float* __restrict__ Wt,
                             const float* __restrict__ bs, const float* __restrict__ bt) {
    const size_t gid = (size_t)blockIdx.x * blockDim.x + threadIdx.x;
    const size_t total = (size_t)Tn * Dn * (Cn / 4);
    if (gid < total) {
        const size_t row = gid >> 7;
        const int    c4  = (int)(gid & 127);
        float4 s = reinterpret_cast<const float4*>(Ws)[row * 128 + c4];
        float4 t = reinterpret_cast<const float4*>(Wt)[row * 128 + c4];
        const size_t wrow = row * Kn;
        write_hl(g_Wh + wrow + c4 * 4,       g_Wl + wrow + c4 * 4,       s);
        write_hl(g_Wh + wrow + 512 + c4 * 4, g_Wl + wrow + 512 + c4 * 4, t);
    }
    if (gid < (size_t)Tn * Dn) g_bias[gid] = bs[gid] + bt[gid];
}

// -------------------- mma.sync grouped GEMM ---------------------------------
// Per stage: 4 tiles of 128 rows x 128 bytes (Ah, Al, Bh, Bl), SW128 swizzle.
__device__ __forceinline__ void load_stage(int s, int buf, int tid,
                                           size_t rowA0, size_t rowB0, uint32_t sb) {
    const size_t colByte = (size_t)s * 128;   // BK*2 bytes
    const uint32_t st = sb + (uint32_t)buf * STAGE_BYTES;
    const char* gAh = (const char*)g_Ah;
    const char* gAl = (const char*)g_Al;
    const char* gWh = (const char*)g_Wh;
    const char* gWl = (const char*)g_Wl;
#pragma unroll
    for (int i = 0; i < 4; ++i) {           // 1024 16B lines per tile / 256 thr
        const int idx = tid + i * 256;
        const int r = idx >> 3;
        const int cb = (idx & 7) * 16;
        const uint32_t sw = SWZ((uint32_t)(r * 128 + cb));
        const size_t goA = (rowA0 + r) * (Kn * 2) + colByte + cb;
        const size_t goB = (rowB0 + r) * (Kn * 2) + colByte + cb;
        CP16(st + sw,                  gAh + goA);
        CP16(st + 16384u + sw,         gAl + goA);
        CP16(st + 32768u + sw,         gWh + goB);
        CP16(st + 49152u + sw,         gWl + goB);
    }
}

__global__ __launch_bounds__(256, 1) void gemm_kernel(float* __restrict__ out) {
    extern __shared__ char smem[];
    const uint32_t sb = smem_u32(smem);
    const int tid = threadIdx.x, wid = tid >> 5, lane = tid & 31;
    const int bn = blockIdx.x, bm = blockIdx.y, t = blockIdx.z;

    const int wm = wid & 3;          // 4 warps in M
    const int wn = wid >> 2;         // 2 warps in N
    const int mbase = wm * 32;
    const int nbase = wn * 64;

    // per-lane ldmatrix addressing components
    const int tid8 = lane >> 3;                  // which 8x8 tile
    const int r8   = lane & 7;                   // row within tile
    const int rowOff = ((tid8 & 1) << 3) + r8;   // 0..15
    const int colOff = (tid8 >> 1) << 4;         // 0 or 16 bytes

    const size_t rowA0 = (size_t)t * Bn + (size_t)bm * TILE_M;
    const size_t rowB0 = (size_t)t * Dn + (size_t)bn * TILE_N;

    float acc[2][8][4];
#pragma unroll
    for (int i = 0; i < 2; ++i)
#pragma unroll
        for (int j = 0; j < 8; ++j)
#pragma unroll
            for (int q = 0; q < 4; ++q) acc[i][j][q] = 0.f;

    load_stage(0, 0, tid, rowA0, rowB0, sb); CP_COMMIT();
    load_stage(1, 1, tid, rowA0, rowB0, sb); CP_COMMIT();

    for (int ks = 0; ks < NSTAGE; ++ks) {
        const int buf = ks % PIPE;
        CP_WAIT_1();
        __syncthreads();
        if (ks + 2 < NSTAGE) load_stage(ks + 2, (ks + 2) % PIPE, tid, rowA0, rowB0, sb);
        CP_COMMIT();

        const uint32_t st  = sb + (uint32_t)buf * STAGE_BYTES;
        const uint32_t aHb = st, aLb = st + 16384u;
        const uint32_t bHb = st + 32768u, bLb = st + 49152u;

#pragma unroll
        for (int kk = 0; kk < 4; ++kk) {     // 4 k16 chunks per stage
            const int kcb = kk * 32 + colOff;
            uint32_t ah[2][4], al[2][4], bh[4][4], bl[4][4];
#pragma unroll
            for (int mf = 0; mf < 2; ++mf) {
                const uint32_t o = SWZ((uint32_t)((mbase + mf * 16 + rowOff) * 128 + kcb));
                ldsm4(ah[mf], aHb + o);
                ldsm4(al[mf], aLb + o);
            }
#pragma unroll
            for (int g = 0; g < 4; ++g) {
                const uint32_t o = SWZ((uint32_t)((nbase + g * 16 + rowOff) * 128 + kcb));
                ldsm4(bh[g], bHb + o);
                ldsm4(bl[g], bLb + o);
            }
#pragma unroll
            for (int mf = 0; mf < 2; ++mf) {
#pragma unroll
                for (int g = 0; g < 4; ++g) {
                    // n8 frag even: {b[0],b[2]}, odd: {b[1],b[3]}
                    mma16816(acc[mf][g * 2 + 0], ah[mf], bh[g][0], bh[g][2]);
                    mma16816(acc[mf][g * 2 + 1], ah[mf], bh[g][1], bh[g][3]);
                    mma16816(acc[mf][g * 2 + 0], ah[mf], bl[g][0], bl[g][2]);
                    mma16816(acc[mf][g * 2 + 1], ah[mf], bl[g][1], bl[g][3]);
                    mma16816(acc[mf][g * 2 + 0], al[mf], bh[g][0], bh[g][2]);
                    mma16816(acc[mf][g * 2 + 1], al[mf], bh[g][1], bh[g][3]);
                }
            }
        }
        __syncthreads();
    }

    // -------------------- epilogue: bias + store --------------------
    const int qrow = lane >> 2;        // 0..7
    const int qcol = (lane & 3) * 2;   // 0,2,4,6
#pragma unroll
    for (int mf = 0; mf < 2; ++mf) {
        const size_t row0 = (size_t)bm * TILE_M + mbase + mf * 16 + qrow;
#pragma unroll
        for (int nf = 0; nf < 8; ++nf) {
            const int col = bn * TILE_N + nbase + nf * 8 + qcol;
            const float2 bv = *reinterpret_cast<const float2*>(g_bias + t * Dn + col);
            float2 o0, o1;
            o0.x = acc[mf][nf][0] + bv.x;
            o0.y = acc[mf][nf][1] + bv.y;
            o1.x = acc[mf][nf][2] + bv.x;
            o1.y = acc[mf][nf][3] + bv.y;
            *reinterpret_cast<float2*>(out + row0 * (Tn * Dn) + (size_t)t * Dn + col) = o0;
            *reinterpret_cast<float2*>(out + (row0 + 8) * (Tn * Dn) + (size_t)t * Dn + col) = o1;
        }
    }
}

// ---------------------------------------------------------------------------
extern "C" void kernel_launch(void* const* d_in, const int* in_sizes, int n_in,
                              void* d_out, int out_size) {
    const float* x  = (const float*)d_in[0];
    const float* Ws = (const float*)d_in[1];
    const float* bs = (const float*)d_in[2];
    const float* Wt = (const float*)d_in[3];
    const float* bt = (const float*)d_in[4];
    float* out = (float*)d_out;

    cudaFuncSetAttribute(gemm_kernel, cudaFuncAttributeMaxDynamicSharedMemorySize, SMEM_TOTAL);

    prep_kernel<<<Bn, 128>>>(x);

    const size_t wtotal = (size_t)Tn * Dn * (Cn / 4);
    wprep_kernel<<<(unsigned)((wtotal + 255) / 256), 256>>>(Ws, Wt, bs, bt);

    dim3 grid(Dn / TILE_N, Bn / TILE_M, Tn);
    gemm_kernel<<<grid, 256, SMEM_TOTAL>>>(out);
}

// round 4
// speedup vs baseline: 3.3528x; 1.3406x over previous
#include <cuda_runtime.h>
#include <cuda_fp16.h>
#include <cstdint>

#define Tn 17
#define Bn 4096
#define Cn 512
#define Dn 512
#define Kn 1024          // [seasonal | trend] along K
#define TILE_M 128
#define TILE_N 128
#define BK 64            // K elems per stage (128 bytes/row)
#define NSTAGE (Kn / BK) // 16
#define PIPE 3           // smem buffers

// -------------------- scratch (device globals; no runtime alloc) ------------
__device__ __align__(256) __half g_Ah[(size_t)Tn * Bn * Kn];  // ~143 MB
__device__ __align__(256) __half g_Al[(size_t)Tn * Bn * Kn];  // ~143 MB
__device__ __align__(256) __half g_Wh[(size_t)Tn * Dn * Kn];  // ~18 MB
__device__ float g_bias[Tn * Dn];

// -------------------- helpers ------------------------------------------------
__device__ __forceinline__ uint32_t smem_u32(const void* p) {
    uint32_t a;
    asm("{ .reg .u64 t; cvta.to.shared.u64 t, %1; cvt.u32.u64 %0, t; }"
        : "=r"(a) : "l"(p));
    return a;
}

#define SWZ(o) ((o) ^ (((o) >> 3) & 0x70))

#define CP16(smem_addr, gptr) \
    asm volatile("cp.async.cg.shared.global [%0], [%1], 16;" \
                 :: "r"((uint32_t)(smem_addr)), "l"(gptr) : "memory")
#define CP_COMMIT()  asm volatile("cp.async.commit_group;" ::: "memory")
#define CP_WAIT_1()  asm volatile("cp.async.wait_group 1;" ::: "memory")

__device__ __forceinline__ void ldsm4(uint32_t* r, uint32_t addr) {
    asm volatile("ldmatrix.sync.aligned.m8n8.x4.shared.b16 {%0,%1,%2,%3}, [%4];"
                 : "=r"(r[0]), "=r"(r[1]), "=r"(r[2]), "=r"(r[3]) : "r"(addr));
}

__device__ __forceinline__ void mma16816(float* c, const uint32_t* a,
                                         uint32_t b0, uint32_t b1) {
    asm volatile(
        "mma.sync.aligned.m16n8k16.row.col.f32.f16.f16.f32 "
        "{%0,%1,%2,%3}, {%4,%5,%6,%7}, {%8,%9}, {%0,%1,%2,%3};"
        : "+f"(c[0]), "+f"(c[1]), "+f"(c[2]), "+f"(c[3])
        : "r"(a[0]), "r"(a[1]), "r"(a[2]), "r"(a[3]), "r"(b0), "r"(b1));
}

// SMEM: PIPE stages x (Ah 16K | Al 16K | Bh 16K) = 3 x 48K = 144K
#define STAGE_BYTES 49152u
#define SMEM_TOTAL  (PIPE * STAGE_BYTES)

// -------------------- prep: seasonal/trend -> fp16 hi/lo --------------------
__device__ __forceinline__ void write_hl(__half* ph, __half* pl, float4 v) {
    float a[4] = {v.x, v.y, v.z, v.w};
    uint2 uh, ul;
    unsigned short h[4], l[4];
#pragma unroll
    for (int i = 0; i < 4; ++i) {
        __half hb = __float2half_rn(a[i]);
        __half lb = __float2half_rn(a[i] - __half2float(hb));
        h[i] = __half_as_ushort(hb);
        l[i] = __half_as_ushort(lb);
    }
    uh.x = (uint32_t)h[0] | ((uint32_t)h[1] << 16);
    uh.y = (uint32_t)h[2] | ((uint32_t)h[3] << 16);
    ul.x = (uint32_t)l[0] | ((uint32_t)l[1] << 16);
    ul.y = (uint32_t)l[2] | ((uint32_t)l[3] << 16);
    *reinterpret_cast<uint2*>(ph) = uh;
    *reinterpret_cast<uint2*>(pl) = ul;
}

__global__ void prep_kernel(const float* __restrict__ x) {
    const int b  = blockIdx.x;
    const int c4 = threadIdx.x;  // 0..127
    const float4* xb = reinterpret_cast<const float4*>(x) + (size_t)b * (Tn * Cn / 4);

    float4 v[Tn];
    float sx = 0.f, sy = 0.f, sz = 0.f, sw = 0.f;
#pragma unroll
    for (int t = 0; t < Tn; ++t) {
        v[t] = xb[t * (Cn / 4) + c4];
        sx += v[t].x; sy += v[t].y; sz += v[t].z; sw += v[t].w;
    }
    const float4 x0 = v[0];
    const float4 xl = v[Tn - 1];
    const float inv = 1.0f / 37.0f;

#pragma unroll
    for (int t = 0; t < Tn; ++t) {
        const float a = (float)(18 - t);
        const float c = (float)(t + 2);
        float4 tr, se;
        tr.x = (sx + a * x0.x + c * xl.x) * inv;
        tr.y = (sy + a * x0.y + c * xl.y) * inv;
        tr.z = (sz + a * x0.z + c * xl.z) * inv;
        tr.w = (sw + a * x0.w + c * xl.w) * inv;
        se.x = v[t].x - tr.x; se.y = v[t].y - tr.y;
        se.z = v[t].z - tr.z; se.w = v[t].w - tr.w;
        const size_t row = ((size_t)t * Bn + b) * Kn;
        write_hl(g_Ah + row + c4 * 4,       g_Al + row + c4 * 4,       se);
        write_hl(g_Ah + row + 512 + c4 * 4, g_Al + row + 512 + c4 * 4, tr);
    }
}

__global__ void wprep_kernel(const float* __restrict__ Ws, const float* __restrict__ Wt,
                             const float* __restrict__ bs, const float* __restrict__ bt) {
    const size_t gid = (size_t)blockIdx.x * blockDim.x + threadIdx.x;
    const size_t total = (size_t)Tn * Dn * (Cn / 4);
    if (gid < total) {
        const size_t row = gid >> 7;
        const int    c4  = (int)(gid & 127);
        float4 s = reinterpret_cast<const float4*>(Ws)[row * 128 + c4];
        float4 t = reinterpret_cast<const float4*>(Wt)[row * 128 + c4];
        const size_t wrow = row * Kn;
        // fp16 hi only for weights (Ah*Bl term dropped)
        float as[4] = {s.x, s.y, s.z, s.w};
        float at[4] = {t.x, t.y, t.z, t.w};
        uint2 us, ut;
        unsigned short hs[4], ht[4];
#pragma unroll
        for (int i = 0; i < 4; ++i) {
            hs[i] = __half_as_ushort(__float2half_rn(as[i]));
            ht[i] = __half_as_ushort(__float2half_rn(at[i]));
        }
        us.x = (uint32_t)hs[0] | ((uint32_t)hs[1] << 16);
        us.y = (uint32_t)hs[2] | ((uint32_t)hs[3] << 16);
        ut.x = (uint32_t)ht[0] | ((uint32_t)ht[1] << 16);
        ut.y = (uint32_t)ht[2] | ((uint32_t)ht[3] << 16);
        *reinterpret_cast<uint2*>(g_Wh + wrow + c4 * 4)       = us;
        *reinterpret_cast<uint2*>(g_Wh + wrow + 512 + c4 * 4) = ut;
    }
    if (gid < (size_t)Tn * Dn) g_bias[gid] = bs[gid] + bt[gid];
}

// -------------------- mma.sync grouped GEMM ---------------------------------
// Per stage: 3 tiles of 128 rows x 128 bytes (Ah, Al, Bh), SW128 swizzle.
__device__ __forceinline__ void load_stage(int s, int buf, int tid,
                                           size_t rowA0, size_t rowB0, uint32_t sb) {
    const size_t colByte = (size_t)s * 128;   // BK*2 bytes
    const uint32_t st = sb + (uint32_t)buf * STAGE_BYTES;
    const char* gAh = (const char*)g_Ah;
    const char* gAl = (const char*)g_Al;
    const char* gWh = (const char*)g_Wh;
#pragma unroll
    for (int i = 0; i < 4; ++i) {           // 1024 16B lines per tile / 256 thr
        const int idx = tid + i * 256;
        const int r = idx >> 3;
        const int cb = (idx & 7) * 16;
        const uint32_t sw = SWZ((uint32_t)(r * 128 + cb));
        const size_t goA = (rowA0 + r) * (Kn * 2) + colByte + cb;
        const size_t goB = (rowB0 + r) * (Kn * 2) + colByte + cb;
        CP16(st + sw,          gAh + goA);
        CP16(st + 16384u + sw, gAl + goA);
        CP16(st + 32768u + sw, gWh + goB);
    }
}

__global__ __launch_bounds__(256, 1) void gemm_kernel(float* __restrict__ out) {
    extern __shared__ char smem[];
    const uint32_t sb = smem_u32(smem);
    const int tid = threadIdx.x, wid = tid >> 5, lane = tid & 31;
    const int bn = blockIdx.x, bm = blockIdx.y, t = blockIdx.z;

    const int wm = wid & 3;          // 4 warps in M
    const int wn = wid >> 2;         // 2 warps in N
    const int mbase = wm * 32;
    const int nbase = wn * 64;

    const int tid8 = lane >> 3;
    const int r8   = lane & 7;
    const int rowOff = ((tid8 & 1) << 3) + r8;   // 0..15
    const int colOff = (tid8 >> 1) << 4;         // 0 or 16 bytes

    const size_t rowA0 = (size_t)t * Bn + (size_t)bm * TILE_M;
    const size_t rowB0 = (size_t)t * Dn + (size_t)bn * TILE_N;

    float acc[2][8][4];
#pragma unroll
    for (int i = 0; i < 2; ++i)
#pragma unroll
        for (int j = 0; j < 8; ++j)
#pragma unroll
            for (int q = 0; q < 4; ++q) acc[i][j][q] = 0.f;

    load_stage(0, 0, tid, rowA0, rowB0, sb); CP_COMMIT();
    load_stage(1, 1, tid, rowA0, rowB0, sb); CP_COMMIT();

    for (int ks = 0; ks < NSTAGE; ++ks) {
        const int buf = ks % PIPE;
        CP_WAIT_1();
        __syncthreads();
        if (ks + 2 < NSTAGE) load_stage(ks + 2, (ks + 2) % PIPE, tid, rowA0, rowB0, sb);
        CP_COMMIT();

        const uint32_t st  = sb + (uint32_t)buf * STAGE_BYTES;
        const uint32_t aHb = st, aLb = st + 16384u;
        const uint32_t bHb = st + 32768u;

#pragma unroll
        for (int kk = 0; kk < 4; ++kk) {     // 4 k16 chunks per stage
            const int kcb = kk * 32 + colOff;
            uint32_t ah[2][4], al[2][4], bh[4][4];
#pragma unroll
            for (int mf = 0; mf < 2; ++mf) {
                const uint32_t o = SWZ((uint32_t)((mbase + mf * 16 + rowOff) * 128 + kcb));
                ldsm4(ah[mf], aHb + o);
                ldsm4(al[mf], aLb + o);
            }
#pragma unroll
            for (int g = 0; g < 4; ++g) {
                const uint32_t o = SWZ((uint32_t)((nbase + g * 16 + rowOff) * 128 + kcb));
                ldsm4(bh[g], bHb + o);
            }
            // term 1: Ah*Bh — 16 independent MMAs
#pragma unroll
            for (int mf = 0; mf < 2; ++mf)
#pragma unroll
                for (int g = 0; g < 4; ++g) {
                    mma16816(acc[mf][g * 2 + 0], ah[mf], bh[g][0], bh[g][2]);
                    mma16816(acc[mf][g * 2 + 1], ah[mf], bh[g][1], bh[g][3]);
                }
            // term 2: Al*Bh — acc reuse distance = 16 MMAs
#pragma unroll
            for (int mf = 0; mf < 2; ++mf)
#pragma unroll
                for (int g = 0; g < 4; ++g) {
                    mma16816(acc[mf][g * 2 + 0], al[mf], bh[g][0], bh[g][2]);
                    mma16816(acc[mf][g * 2 + 1], al[mf], bh[g][1], bh[g][3]);
                }
        }
        __syncthreads();
    }

    // -------------------- epilogue: bias + store --------------------
    const int qrow = lane >> 2;
    const int qcol = (lane & 3) * 2;
#pragma unroll
    for (int mf = 0; mf < 2; ++mf) {
        const size_t row0 = (size_t)bm * TILE_M + mbase + mf * 16 + qrow;
#pragma unroll
        for (int nf = 0; nf < 8; ++nf) {
            const int col = bn * TILE_N + nbase + nf * 8 + qcol;
            const float2 bv = *reinterpret_cast<const float2*>(g_bias + t * Dn + col);
            float2 o0, o1;
            o0.x = acc[mf][nf][0] + bv.x;
            o0.y = acc[mf][nf][1] + bv.y;
            o1.x = acc[mf][nf][2] + bv.x;
            o1.y = acc[mf][nf][3] + bv.y;
            *reinterpret_cast<float2*>(out + row0 * (Tn * Dn) + (size_t)t * Dn + col) = o0;
            *reinterpret_cast<float2*>(out + (row0 + 8) * (Tn * Dn) + (size_t)t * Dn + col) = o1;
        }
    }
}

// ---------------------------------------------------------------------------
extern "C" void kernel_launch(void* const* d_in, const int* in_sizes, int n_in,
                              void* d_out, int out_size) {
    const float* x  = (const float*)d_in[0];
    const float* Ws = (const float*)d_in[1];
    const float* bs = (const float*)d_in[2];
    const float* Wt = (const float*)d_in[3];
    const float* bt = (const float*)d_in[4];
    float* out = (float*)d_out;

    cudaFuncSetAttribute(gemm_kernel, cudaFuncAttributeMaxDynamicSharedMemorySize, SMEM_TOTAL);

    prep_kernel<<<Bn, 128>>>(x);

    const size_t wtotal = (size_t)Tn * Dn * (Cn / 4);
    wprep_kernel<<<(unsigned)((wtotal + 255) / 256), 256>>>(Ws, Wt, bs, bt);

    dim3 grid(Dn / TILE_N, Bn / TILE_M, Tn);
    gemm_kernel<<<grid, 256, SMEM_TOTAL>>>(out);
}

// round 5
// speedup vs baseline: 6.1336x; 1.8294x over previous
#include <cuda_runtime.h>
#include <cuda_fp16.h>
#include <cstdint>

#define Tn 17
#define Bn 4096
#define Cn 512
#define Dn 512
#define Kn 1024          // [seasonal | trend] along K
#define TILE_M 128
#define TILE_N 256
#define BK 64            // K elems per stage (128 bytes/row)
#define NSTAGE (Kn / BK) // 16
#define PIPE 4

// -------------------- scratch (device globals; no runtime alloc) ------------
__device__ __align__(256) __half g_A[(size_t)Tn * Bn * Kn];  // ~143 MB
__device__ __align__(256) __half g_W[(size_t)Tn * Dn * Kn];  // ~18 MB
__device__ float g_bias[Tn * Dn];

// -------------------- helpers ------------------------------------------------
__device__ __forceinline__ uint32_t smem_u32(const void* p) {
    uint32_t a;
    asm("{ .reg .u64 t; cvta.to.shared.u64 t, %1; cvt.u32.u64 %0, t; }"
        : "=r"(a) : "l"(p));
    return a;
}

#define SWZ(o) ((o) ^ (((o) >> 3) & 0x70))

#define CP16(smem_addr, gptr) \
    asm volatile("cp.async.cg.shared.global [%0], [%1], 16;" \
                 :: "r"((uint32_t)(smem_addr)), "l"(gptr) : "memory")
#define CP_COMMIT()  asm volatile("cp.async.commit_group;" ::: "memory")
#define CP_WAIT_2()  asm volatile("cp.async.wait_group 2;" ::: "memory")

__device__ __forceinline__ void ldsm4(uint32_t* r, uint32_t addr) {
    asm volatile("ldmatrix.sync.aligned.m8n8.x4.shared.b16 {%0,%1,%2,%3}, [%4];"
                 : "=r"(r[0]), "=r"(r[1]), "=r"(r[2]), "=r"(r[3]) : "r"(addr));
}

__device__ __forceinline__ void mma16816(float* c, const uint32_t* a,
                                         uint32_t b0, uint32_t b1) {
    asm volatile(
        "mma.sync.aligned.m16n8k16.row.col.f32.f16.f16.f32 "
        "{%0,%1,%2,%3}, {%4,%5,%6,%7}, {%8,%9}, {%0,%1,%2,%3};"
        : "+f"(c[0]), "+f"(c[1]), "+f"(c[2]), "+f"(c[3])
        : "r"(a[0]), "r"(a[1]), "r"(a[2]), "r"(a[3]), "r"(b0), "r"(b1));
}

// SMEM: PIPE stages x (A 16K | B 32K) = 4 x 48K = 192K
#define STAGE_BYTES 49152u
#define SMEM_TOTAL  (PIPE * STAGE_BYTES)

// -------------------- prep: seasonal/trend -> fp16 ---------------------------
__device__ __forceinline__ void write_h(__half* ph, float4 v) {
    float a[4] = {v.x, v.y, v.z, v.w};
    uint2 uh;
    unsigned short h[4];
#pragma unroll
    for (int i = 0; i < 4; ++i) h[i] = __half_as_ushort(__float2half_rn(a[i]));
    uh.x = (uint32_t)h[0] | ((uint32_t)h[1] << 16);
    uh.y = (uint32_t)h[2] | ((uint32_t)h[3] << 16);
    *reinterpret_cast<uint2*>(ph) = uh;
}

__global__ void prep_kernel(const float* __restrict__ x) {
    const int b  = blockIdx.x;
    const int c4 = threadIdx.x;  // 0..127
    const float4* xb = reinterpret_cast<const float4*>(x) + (size_t)b * (Tn * Cn / 4);

    float4 v[Tn];
    float sx = 0.f, sy = 0.f, sz = 0.f, sw = 0.f;
#pragma unroll
    for (int t = 0; t < Tn; ++t) {
        v[t] = xb[t * (Cn / 4) + c4];
        sx += v[t].x; sy += v[t].y; sz += v[t].z; sw += v[t].w;
    }
    const float4 x0 = v[0];
    const float4 xl = v[Tn - 1];
    const float inv = 1.0f / 37.0f;

#pragma unroll
    for (int t = 0; t < Tn; ++t) {
        const float a = (float)(18 - t);
        const float c = (float)(t + 2);
        float4 tr, se;
        tr.x = (sx + a * x0.x + c * xl.x) * inv;
        tr.y = (sy + a * x0.y + c * xl.y) * inv;
        tr.z = (sz + a * x0.z + c * xl.z) * inv;
        tr.w = (sw + a * x0.w + c * xl.w) * inv;
        se.x = v[t].x - tr.x; se.y = v[t].y - tr.y;
        se.z = v[t].z - tr.z; se.w = v[t].w - tr.w;
        const size_t row = ((size_t)t * Bn + b) * Kn;
        write_h(g_A + row + c4 * 4,       se);
        write_h(g_A + row + 512 + c4 * 4, tr);
    }
}

__global__ void wprep_kernel(const float* __restrict__ Ws, const float* __restrict__ Wt,
                             const float* __restrict__ bs, const float* __restrict__ bt) {
    const size_t gid = (size_t)blockIdx.x * blockDim.x + threadIdx.x;
    const size_t total = (size_t)Tn * Dn * (Cn / 4);
    if (gid < total) {
        const size_t row = gid >> 7;
        const int    c4  = (int)(gid & 127);
        float4 s = reinterpret_cast<const float4*>(Ws)[row * 128 + c4];
        float4 t = reinterpret_cast<const float4*>(Wt)[row * 128 + c4];
        const size_t wrow = row * Kn;
        write_h(g_W + wrow + c4 * 4,       s);
        write_h(g_W + wrow + 512 + c4 * 4, t);
    }
    if (gid < (size_t)Tn * Dn) g_bias[gid] = bs[gid] + bt[gid];
}

// -------------------- mma.sync grouped GEMM ---------------------------------
// Stage: A 128 rows x 128B (16K) then B 256 rows x 128B (32K), SW128 swizzle.
__device__ __forceinline__ void load_stage(int s, int buf, int tid,
                                           size_t rowA0, size_t rowB0, uint32_t sb) {
    const size_t colByte = (size_t)s * 128;
    const uint32_t st = sb + (uint32_t)buf * STAGE_BYTES;
    const char* gA = (const char*)g_A;
    const char* gW = (const char*)g_W;
#pragma unroll
    for (int i = 0; i < 2; ++i) {           // A: 1024 lines / 512 thr
        const int idx = tid + i * 512;
        const int r = idx >> 3;
        const int cb = (idx & 7) * 16;
        const uint32_t sw = SWZ((uint32_t)(r * 128 + cb));
        CP16(st + sw, gA + (rowA0 + r) * (Kn * 2) + colByte + cb);
    }
#pragma unroll
    for (int i = 0; i < 4; ++i) {           // B: 2048 lines / 512 thr
        const int idx = tid + i * 512;
        const int r = idx >> 3;
        const int cb = (idx & 7) * 16;
        const uint32_t sw = SWZ((uint32_t)(r * 128 + cb));
        CP16(st + 16384u + sw, gW + (rowB0 + r) * (Kn * 2) + colByte + cb);
    }
}

__global__ __launch_bounds__(512, 1) void gemm_kernel(float* __restrict__ out) {
    extern __shared__ char smem[];
    const uint32_t sb = smem_u32(smem);
    const int tid = threadIdx.x, wid = tid >> 5, lane = tid & 31;
    const int bn = blockIdx.x, bm = blockIdx.y, t = blockIdx.z;

    const int wm = wid & 3;          // 4 warps in M
    const int wn = wid >> 2;         // 4 warps in N
    const int mbase = wm * 32;
    const int nbase = wn * 64;

    const int tid8 = lane >> 3;
    const int r8   = lane & 7;
    const int rowOff = ((tid8 & 1) << 3) + r8;   // 0..15
    const int colOff = (tid8 >> 1) << 4;         // 0 or 16 bytes

    const size_t rowA0 = (size_t)t * Bn + (size_t)bm * TILE_M;
    const size_t rowB0 = (size_t)t * Dn + (size_t)bn * TILE_N;

    float acc[2][8][4];
#pragma unroll
    for (int i = 0; i < 2; ++i)
#pragma unroll
        for (int j = 0; j < 8; ++j)
#pragma unroll
            for (int q = 0; q < 4; ++q) acc[i][j][q] = 0.f;

    load_stage(0, 0, tid, rowA0, rowB0, sb); CP_COMMIT();
    load_stage(1, 1, tid, rowA0, rowB0, sb); CP_COMMIT();
    load_stage(2, 2, tid, rowA0, rowB0, sb); CP_COMMIT();

    for (int ks = 0; ks < NSTAGE; ++ks) {
        const int buf = ks % PIPE;
        CP_WAIT_2();
        __syncthreads();
        if (ks + 3 < NSTAGE) load_stage(ks + 3, (ks + 3) % PIPE, tid, rowA0, rowB0, sb);
        CP_COMMIT();

        const uint32_t st = sb + (uint32_t)buf * STAGE_BYTES;
        const uint32_t aB = st, bB = st + 16384u;

#pragma unroll
        for (int kk = 0; kk < 4; ++kk) {     // 4 k16 chunks per stage
            const int kcb = kk * 32 + colOff;
            uint32_t ah[2][4], bh[4][4];
#pragma unroll
            for (int mf = 0; mf < 2; ++mf) {
                const uint32_t o = SWZ((uint32_t)((mbase + mf * 16 + rowOff) * 128 + kcb));
                ldsm4(ah[mf], aB + o);
            }
#pragma unroll
            for (int g = 0; g < 4; ++g) {
                const uint32_t o = SWZ((uint32_t)((nbase + g * 16 + rowOff) * 128 + kcb));
                ldsm4(bh[g], bB + o);
            }
#pragma unroll
            for (int mf = 0; mf < 2; ++mf)
#pragma unroll
                for (int g = 0; g < 4; ++g) {
                    mma16816(acc[mf][g * 2 + 0], ah[mf], bh[g][0], bh[g][2]);
                    mma16816(acc[mf][g * 2 + 1], ah[mf], bh[g][1], bh[g][3]);
                }
        }
        __syncthreads();
    }

    // -------------------- epilogue: bias + store --------------------
    const int qrow = lane >> 2;
    const int qcol = (lane & 3) * 2;
#pragma unroll
    for (int mf = 0; mf < 2; ++mf) {
        const size_t row0 = (size_t)bm * TILE_M + mbase + mf * 16 + qrow;
#pragma unroll
        for (int nf = 0; nf < 8; ++nf) {
            const int col = bn * TILE_N + nbase + nf * 8 + qcol;
            const float2 bv = *reinterpret_cast<const float2*>(g_bias + t * Dn + col);
            float2 o0, o1;
            o0.x = acc[mf][nf][0] + bv.x;
            o0.y = acc[mf][nf][1] + bv.y;
            o1.x = acc[mf][nf][2] + bv.x;
            o1.y = acc[mf][nf][3] + bv.y;
            *reinterpret_cast<float2*>(out + row0 * (Tn * Dn) + (size_t)t * Dn + col) = o0;
            *reinterpret_cast<float2*>(out + (row0 + 8) * (Tn * Dn) + (size_t)t * Dn + col) = o1;
        }
    }
}

// ---------------------------------------------------------------------------
extern "C" void kernel_launch(void* const* d_in, const int* in_sizes, int n_in,
                              void* d_out, int out_size) {
    const float* x  = (const float*)d_in[0];
    const float* Ws = (const float*)d_in[1];
    const float* bs = (const float*)d_in[2];
    const float* Wt = (const float*)d_in[3];
    const float* bt = (const float*)d_in[4];
    float* out = (float*)d_out;

    cudaFuncSetAttribute(gemm_kernel, cudaFuncAttributeMaxDynamicSharedMemorySize, SMEM_TOTAL);

    prep_kernel<<<Bn, 128>>>(x);

    const size_t wtotal = (size_t)Tn * Dn * (Cn / 4);
    wprep_kernel<<<(unsigned)((wtotal + 255) / 256), 256>>>(Ws, Wt, bs, bt);

    dim3 grid(Dn / TILE_N, Bn / TILE_M, Tn);
    gemm_kernel<<<grid, 512, SMEM_TOTAL>>>(out);
}